// round 4
// baseline (speedup 1.0000x reference)
#include <cuda_runtime.h>
#include <cstdint>
#include <cstddef>

#define DI __device__ __forceinline__

// ---------------- constants ----------------
constexpr int DIMK = 1024;
constexpr int BATCH = 16384;
constexpr size_t PLANE = (size_t)BATCH * DIMK;

// GEMM tiling (int8): CTA 128x64, K-chunk 64, 4 stages
constexpr int BM = 128, BN = 64, BK = 64, THREADS = 256;
constexpr int CHUNKS = 32;                        // 2048 / 64
constexpr uint32_t A_PLANE = 128 * 64;            // 8192 B
constexpr uint32_t B_PLANE = 64 * 64;             // 4096 B
constexpr uint32_t STG = 2 * A_PLANE + 2 * B_PLANE;   // 24576
constexpr uint32_t SMEM_TOTAL = 4 * STG;          // 98304 -> 2 CTAs/SM

// ---------------- device scratch (static: allowed) ----------------
__device__ int8_t g_Ahi[(size_t)BATCH * 2048];    // [m][k] k = [X row | H row]
__device__ int8_t g_Alo[(size_t)BATCH * 2048];
__device__ int8_t g_Whi[(size_t)4096 * 2048];     // [(gate*1024+n)][k] transposed
__device__ int8_t g_Wlo[(size_t)4096 * 2048];
__device__ float  g_sa[BATCH];
__device__ float  g_sw[4096];
__device__ float  g_swinv[4096];
__device__ float  g_z[4 * PLANE];                 // pre-activations

// ---------------- PTX helpers (baseline features only) ----------------
DI uint32_t smem_u32(const void* p) {
    uint32_t a;
    asm("{ .reg .u64 t; cvta.to.shared.u64 t, %1; cvt.u32.u64 %0, t; }" : "=r"(a) : "l"(p));
    return a;
}
DI uint32_t swz64(uint32_t o) { return o ^ ((o >> 3) & 0x30); }
DI void cpasync16(uint32_t dst, const void* src) {
    asm volatile("cp.async.cg.shared.global [%0], [%1], 16;" :: "r"(dst), "l"(src) : "memory");
}
DI void cpcommit() { asm volatile("cp.async.commit_group;" ::: "memory"); }
template<int N> DI void cpwait() { asm volatile("cp.async.wait_group %0;" :: "n"(N) : "memory"); }
DI void ldsm4(uint32_t* r, uint32_t a) {
    asm volatile("ldmatrix.sync.aligned.m8n8.x4.shared.b16 {%0,%1,%2,%3}, [%4];"
                 : "=r"(r[0]), "=r"(r[1]), "=r"(r[2]), "=r"(r[3]) : "r"(a));
}
DI uint32_t lds32(uint32_t a) {
    uint32_t v;
    asm volatile("ld.shared.b32 %0, [%1];" : "=r"(v) : "r"(a));
    return v;
}
DI void imma32(int* d, const uint32_t* a, uint32_t b0, uint32_t b1) {
    asm volatile(
        "mma.sync.aligned.m16n8k32.row.col.s32.s8.s8.s32 "
        "{%0,%1,%2,%3},{%4,%5,%6,%7},{%8,%9},{%0,%1,%2,%3};"
        : "+r"(d[0]), "+r"(d[1]), "+r"(d[2]), "+r"(d[3])
        : "r"(a[0]), "r"(a[1]), "r"(a[2]), "r"(a[3]), "r"(b0), "r"(b1));
}

DI int clamp127(int v) { return v > 127 ? 127 : (v < -127 ? -127 : v); }

// ---------------- kernel 1: quantize A rows ([X|H] per batch row) ----------------
__global__ void __launch_bounds__(256)
quantA(const float* __restrict__ X, const float* __restrict__ H)
{
    __shared__ float red[8];
    const int m = blockIdx.x, tid = threadIdx.x, lane = tid & 31, wid = tid >> 5;

    const float4 va = reinterpret_cast<const float4*>(X)[(size_t)m * 256 + tid];
    const float4 vb = reinterpret_cast<const float4*>(H)[(size_t)m * 256 + tid];

    float mx = fmaxf(fmaxf(fabsf(va.x), fabsf(va.y)), fmaxf(fabsf(va.z), fabsf(va.w)));
    mx = fmaxf(mx, fmaxf(fmaxf(fabsf(vb.x), fabsf(vb.y)), fmaxf(fabsf(vb.z), fabsf(vb.w))));
    #pragma unroll
    for (int o = 16; o; o >>= 1) mx = fmaxf(mx, __shfl_xor_sync(0xFFFFFFFFu, mx, o));
    if (lane == 0) red[wid] = mx;
    __syncthreads();
    float bm = fmaxf(fmaxf(red[0], red[1]), fmaxf(red[2], red[3]));
    bm = fmaxf(bm, fmaxf(fmaxf(red[4], red[5]), fmaxf(red[6], red[7])));
    const float s   = (bm > 0.f) ? bm / 127.f : 1.f;
    const float inv = (bm > 0.f) ? 127.f / bm : 0.f;
    if (tid == 0) g_sa[m] = s;

    auto quant4 = [&](float4 v, size_t off) {
        char hi[4], lo[4];
        const float* pv = &v.x;
        #pragma unroll
        for (int e = 0; e < 4; ++e) {
            const float q = pv[e] * inv;
            int h = clamp127(__float2int_rn(q));
            int l = clamp127(__float2int_rn((q - (float)h) * 256.f));
            hi[e] = (char)h; lo[e] = (char)l;
        }
        *reinterpret_cast<char4*>(g_Ahi + off) = make_char4(hi[0], hi[1], hi[2], hi[3]);
        *reinterpret_cast<char4*>(g_Alo + off) = make_char4(lo[0], lo[1], lo[2], lo[3]);
    };
    quant4(va, (size_t)m * 2048 + 4 * tid);
    quant4(vb, (size_t)m * 2048 + 1024 + 4 * tid);
}

// ---------------- kernel 2a: W column max -> scales ----------------
__global__ void __launch_bounds__(256)
wmax(const float* __restrict__ Wfx, const float* __restrict__ Wfh,
     const float* __restrict__ Wix, const float* __restrict__ Wih,
     const float* __restrict__ Wox, const float* __restrict__ Woh,
     const float* __restrict__ Wcx, const float* __restrict__ Wch)
{
    const int gate = blockIdx.x >> 2;
    const int n = (blockIdx.x & 3) * 256 + threadIdx.x;
    const float* Wx = (gate == 0) ? Wfx : (gate == 1) ? Wix : (gate == 2) ? Wox : Wcx;
    const float* Wh = (gate == 0) ? Wfh : (gate == 1) ? Wih : (gate == 2) ? Woh : Wch;
    float mx = 0.f;
    for (int k = 0; k < 1024; ++k) mx = fmaxf(mx, fabsf(Wx[(size_t)k * 1024 + n]));
    for (int k = 0; k < 1024; ++k) mx = fmaxf(mx, fabsf(Wh[(size_t)k * 1024 + n]));
    g_sw[gate * 1024 + n]    = (mx > 0.f) ? mx / 127.f : 1.f;
    g_swinv[gate * 1024 + n] = (mx > 0.f) ? 127.f / mx : 0.f;
}

// ---------------- kernel 2b: quantize + transpose W -> [n][k] int8 ----------------
__global__ void __launch_bounds__(256)
wquant(const float* __restrict__ Wfx, const float* __restrict__ Wfh,
       const float* __restrict__ Wix, const float* __restrict__ Wih,
       const float* __restrict__ Wox, const float* __restrict__ Woh,
       const float* __restrict__ Wcx, const float* __restrict__ Wch)
{
    __shared__ int8_t shi[64 * 68];
    __shared__ int8_t slo[64 * 68];
    __shared__ float sinv[64];
    const int gate = blockIdx.x >> 4;
    const int n0 = (blockIdx.x & 15) * 64;
    const int tid = threadIdx.x;
    const float* Wx = (gate == 0) ? Wfx : (gate == 1) ? Wix : (gate == 2) ? Wox : Wcx;
    const float* Wh = (gate == 0) ? Wfh : (gate == 1) ? Wih : (gate == 2) ? Woh : Wch;

    if (tid < 64) sinv[tid] = g_swinv[gate * 1024 + n0 + tid];
    __syncthreads();

    for (int k0 = 0; k0 < 2048; k0 += 64) {
        const float* W = (k0 < 1024) ? Wx : Wh;
        const int kb = k0 & 1023;
        #pragma unroll
        for (int i = 0; i < 16; ++i) {
            const int idx = i * 256 + tid;
            const int kk = idx >> 6, nn = idx & 63;
            const float q = W[(size_t)(kb + kk) * 1024 + n0 + nn] * sinv[nn];
            int h = clamp127(__float2int_rn(q));
            int l = clamp127(__float2int_rn((q - (float)h) * 256.f));
            shi[kk * 68 + nn] = (int8_t)h;
            slo[kk * 68 + nn] = (int8_t)l;
        }
        __syncthreads();
        #pragma unroll
        for (int i = 0; i < 16; ++i) {
            const int idx = i * 256 + tid;
            const int kk = idx & 63, nn = idx >> 6;
            const size_t off = (size_t)(gate * 1024 + n0 + nn) * 2048 + k0 + kk;
            g_Whi[off] = shi[kk * 68 + nn];
            g_Wlo[off] = slo[kk * 68 + nn];
        }
        __syncthreads();
    }
}

// ---------------- kernel 3: int8 split IMMA GEMM ----------------
__global__ void __launch_bounds__(THREADS, 2)
lstm_gemm_i8()
{
    extern __shared__ __align__(1024) char smem[];
    const uint32_t sbase = smem_u32(smem);
    const int tid = threadIdx.x, wid = tid >> 5, lane = tid & 31;

    // 64 consecutive CTAs share the same m-tile (A reuse in L2)
    const int gate = (blockIdx.x >> 4) & 3;
    const int nt   = blockIdx.x & 15;
    const int m0   = (blockIdx.x >> 6) * BM;
    const int wrow = gate * 1024 + nt * 64;       // W row base (n index in g_W*)

    const int warp_m = (wid & 1) * 64;
    const int warp_n = (wid >> 1) * 16;

    int acc1[4][2][4], acc2[4][2][4];
    #pragma unroll
    for (int mi = 0; mi < 4; ++mi)
        #pragma unroll
        for (int j = 0; j < 2; ++j)
            #pragma unroll
            for (int e = 0; e < 4; ++e) { acc1[mi][j][e] = 0; acc2[mi][j][e] = 0; }

    auto stage = [&](int cs, uint32_t sb) {
        const int k0 = cs * BK;
        // A: 2 planes x 128 rows x 4 (16B units)  -> 1024 units
        #pragma unroll
        for (int i = 0; i < 4; ++i) {
            const int idx = i * THREADS + tid;
            const int plane = idx >> 9, u = idx & 511;
            const int r = u >> 2, c = u & 3;
            const int8_t* src = (plane ? g_Alo : g_Ahi) + (size_t)(m0 + r) * 2048 + k0 + c * 16;
            cpasync16(sb + (uint32_t)plane * A_PLANE + swz64((uint32_t)(r * 64 + c * 16)), src);
        }
        // B: 2 planes x 64 rows x 4 units -> 512 units
        #pragma unroll
        for (int i = 0; i < 2; ++i) {
            const int idx = i * THREADS + tid;
            const int plane = idx >> 8, u = idx & 255;
            const int r = u >> 2, c = u & 3;
            const int8_t* src = (plane ? g_Wlo : g_Whi) + (size_t)(wrow + r) * 2048 + k0 + c * 16;
            cpasync16(sb + 2 * A_PLANE + (uint32_t)plane * B_PLANE + swz64((uint32_t)(r * 64 + c * 16)), src);
        }
    };

    stage(0, sbase);           cpcommit();
    stage(1, sbase + STG);     cpcommit();
    stage(2, sbase + 2 * STG); cpcommit();

    #pragma unroll 1
    for (int cc = 0; cc < CHUNKS; ++cc) {
        cpwait<2>();
        __syncthreads();
        if (cc + 3 < CHUNKS) stage(cc + 3, sbase + (uint32_t)((cc + 3) & 3) * STG);
        cpcommit();

        const uint32_t Ab = sbase + (uint32_t)(cc & 3) * STG;
        const uint32_t Bb = Ab + 2 * A_PLANE;

        #pragma unroll
        for (int ks = 0; ks < 2; ++ks) {
            uint32_t ah[4][4], al[4][4];
            #pragma unroll
            for (int mi = 0; mi < 4; ++mi) {
                const uint32_t addr = Ab + swz64((uint32_t)((warp_m + 16 * mi + (lane & 15)) * 64
                                        + ks * 32 + (lane >> 4) * 16));
                ldsm4(ah[mi], addr);
                ldsm4(al[mi], addr + A_PLANE);
            }
            uint32_t bh[2][2], bl[2][2];
            #pragma unroll
            for (int j = 0; j < 2; ++j) {
                const uint32_t o0 = (uint32_t)((warp_n + 8 * j + (lane >> 2)) * 64
                                   + ks * 32 + (lane & 3) * 4);
                const uint32_t a0 = Bb + swz64(o0);
                const uint32_t a1 = Bb + swz64(o0 + 16);
                bh[j][0] = lds32(a0);           bh[j][1] = lds32(a1);
                bl[j][0] = lds32(a0 + B_PLANE); bl[j][1] = lds32(a1 + B_PLANE);
            }
            #pragma unroll
            for (int mi = 0; mi < 4; ++mi)
                #pragma unroll
                for (int j = 0; j < 2; ++j) {
                    imma32(acc1[mi][j], ah[mi], bh[j][0], bh[j][1]);
                    imma32(acc2[mi][j], ah[mi], bl[j][0], bl[j][1]);
                    imma32(acc2[mi][j], al[mi], bh[j][0], bh[j][1]);
                }
        }
    }

    // dequant + store z
    float* zout = g_z + (size_t)gate * PLANE;
    #pragma unroll
    for (int j = 0; j < 2; ++j) {
        const int ncol = nt * 64 + warp_n + 8 * j + 2 * (lane & 3);
        const float2 sw = *reinterpret_cast<const float2*>(&g_sw[gate * 1024 + ncol]);
        #pragma unroll
        for (int mi = 0; mi < 4; ++mi) {
            const int r = m0 + warp_m + 16 * mi + (lane >> 2);
            const float sa0 = g_sa[r], sa1 = g_sa[r + 8];
            const float v0 = (float)acc1[mi][j][0] + (float)acc2[mi][j][0] * 0.00390625f;
            const float v1 = (float)acc1[mi][j][1] + (float)acc2[mi][j][1] * 0.00390625f;
            const float v2 = (float)acc1[mi][j][2] + (float)acc2[mi][j][2] * 0.00390625f;
            const float v3 = (float)acc1[mi][j][3] + (float)acc2[mi][j][3] * 0.00390625f;
            *reinterpret_cast<float2*>(zout + (size_t)r * DIMK + ncol) =
                make_float2(sa0 * sw.x * v0, sa0 * sw.y * v1);
            *reinterpret_cast<float2*>(zout + (size_t)(r + 8) * DIMK + ncol) =
                make_float2(sa1 * sw.x * v2, sa1 * sw.y * v3);
        }
    }
}

// ---------------- kernel 4: epilogue ----------------
__global__ void __launch_bounds__(256)
lstm_epilogue(const int* __restrict__ caro,
              const float* __restrict__ bf, const float* __restrict__ bi,
              const float* __restrict__ bo, const float* __restrict__ bc,
              float* __restrict__ out)
{
    const float cf = (float)__ldg(caro);
    const size_t v = (size_t)blockIdx.x * blockDim.x + threadIdx.x;
    const int col4 = (int)(v & (DIMK / 4 - 1));

    const float4 zf = reinterpret_cast<const float4*>(g_z)[v];
    const float4 zi = reinterpret_cast<const float4*>(g_z + PLANE)[v];
    const float4 zo = reinterpret_cast<const float4*>(g_z + 2 * PLANE)[v];
    const float4 zc = reinterpret_cast<const float4*>(g_z + 3 * PLANE)[v];
    const float4 vbf = reinterpret_cast<const float4*>(bf)[col4];
    const float4 vbi = reinterpret_cast<const float4*>(bi)[col4];
    const float4 vbo = reinterpret_cast<const float4*>(bo)[col4];
    const float4 vbc = reinterpret_cast<const float4*>(bc)[col4];

    float4 h4, c4;
    const float* pzf = &zf.x; const float* pzi = &zi.x;
    const float* pzo = &zo.x; const float* pzc = &zc.x;
    const float* pbf = &vbf.x; const float* pbi = &vbi.x;
    const float* pbo = &vbo.x; const float* pbc = &vbc.x;
    float* ph = &h4.x; float* pc = &c4.x;
    #pragma unroll
    for (int e = 0; e < 4; ++e) {
        const float f  = 1.f / (1.f + expf(-(pzf[e] + pbf[e])));
        const float ii = 1.f / (1.f + expf(-(pzi[e] + pbi[e])));
        const float oo = 1.f / (1.f + expf(-(pzo[e] + pbo[e])));
        const float gg = tanhf(pzc[e] + pbc[e]);
        const float cv = f * cf + ii * gg;
        pc[e] = cv;
        ph[e] = oo * cv;
    }
    reinterpret_cast<float4*>(out)[v] = h4;
    reinterpret_cast<float4*>(out + PLANE)[v] = c4;
}

// ---------------- launch ----------------
extern "C" void kernel_launch(void* const* d_in, const int* in_sizes, int n_in,
                              void* d_out, int out_size) {
    (void)in_sizes; (void)n_in; (void)out_size;
    const float* X    = (const float*)d_in[0];
    const float* H    = (const float*)d_in[1];
    const int*   caro = (const int*)d_in[2];
    const float* Wfx = (const float*)d_in[3];
    const float* Wfh = (const float*)d_in[4];
    const float* bf  = (const float*)d_in[5];
    const float* Wix = (const float*)d_in[6];
    const float* Wih = (const float*)d_in[7];
    const float* bi  = (const float*)d_in[8];
    const float* Wox = (const float*)d_in[9];
    const float* Woh = (const float*)d_in[10];
    const float* bo  = (const float*)d_in[11];
    const float* Wcx = (const float*)d_in[12];
    const float* Wch = (const float*)d_in[13];
    const float* bc  = (const float*)d_in[14];
    float* out = (float*)d_out;

    cudaFuncSetAttribute(lstm_gemm_i8, cudaFuncAttributeMaxDynamicSharedMemorySize, SMEM_TOTAL);

    quantA<<<BATCH, 256>>>(X, H);
    wmax<<<16, 256>>>(Wfx, Wfh, Wix, Wih, Wox, Woh, Wcx, Wch);
    wquant<<<64, 256>>>(Wfx, Wfh, Wix, Wih, Wox, Woh, Wcx, Wch);
    lstm_gemm_i8<<<(BATCH / BM) * 64, THREADS, SMEM_TOTAL>>>();
    lstm_epilogue<<<(int)(PLANE / 4 / 256), 256>>>(caro, bf, bi, bo, bc, out);
}

// round 5
// speedup vs baseline: 3.7837x; 3.7837x over previous
#include <cuda_runtime.h>
#include <cstdint>
#include <cstddef>

#define DI __device__ __forceinline__

// ---------------- constants ----------------
constexpr int BM = 128, BN = 256, BK = 32, THREADS = 256;
constexpr int DIMK = 1024;
constexpr int BATCH = 16384;
constexpr int CHUNKS = 64;                       // 2048 / 32
constexpr size_t PLANE = (size_t)BATCH * DIMK;

constexpr uint32_t A_BYTES = 128 * 128;          // 128 rows x 32 tf32 x 4B (sw128 rows)
constexpr uint32_t B_STRIDE = 1056;              // 256 floats + 8 pad -> conflict-free
constexpr uint32_t B_BYTES = 32 * B_STRIDE;      // 33792
constexpr uint32_t STG = A_BYTES + B_BYTES;      // 50176
constexpr uint32_t SMEM_TOTAL = 4 * STG;         // 200704 (1 CTA/SM)

// z scratch: 4 gates of [16384 x 1024] fp32 pre-activations
__device__ float g_z[4 * PLANE];

// ---------------- PTX helpers ----------------
DI uint32_t smem_u32(const void* p) {
    uint32_t a;
    asm("{ .reg .u64 t; cvta.to.shared.u64 t, %1; cvt.u32.u64 %0, t; }" : "=r"(a) : "l"(p));
    return a;
}
DI uint32_t sw128(uint32_t o) { return o ^ ((o >> 3) & 0x70); }
DI void cpasync16(uint32_t dst, const void* src) {
    asm volatile("cp.async.cg.shared.global [%0], [%1], 16;" :: "r"(dst), "l"(src) : "memory");
}
DI void cpcommit() { asm volatile("cp.async.commit_group;" ::: "memory"); }
template<int N> DI void cpwait() { asm volatile("cp.async.wait_group %0;" :: "n"(N) : "memory"); }
DI void ldsm4(uint32_t* r, uint32_t a) {
    asm volatile("ldmatrix.sync.aligned.m8n8.x4.shared.b16 {%0,%1,%2,%3}, [%4];"
                 : "=r"(r[0]), "=r"(r[1]), "=r"(r[2]), "=r"(r[3]) : "r"(a));
}
DI uint32_t lds32(uint32_t a) {
    uint32_t v;
    asm volatile("ld.shared.b32 %0, [%1];" : "=r"(v) : "r"(a));
    return v;
}
DI void mma8(float* d, const uint32_t* a, uint32_t b0, uint32_t b1) {
    asm volatile(
        "mma.sync.aligned.m16n8k8.row.col.f32.tf32.tf32.f32 "
        "{%0,%1,%2,%3},{%4,%5,%6,%7},{%8,%9},{%0,%1,%2,%3};"
        : "+f"(d[0]), "+f"(d[1]), "+f"(d[2]), "+f"(d[3])
        : "r"(a[0]), "r"(a[1]), "r"(a[2]), "r"(a[3]), "r"(b0), "r"(b1));
}

// ---------------- GEMM: z[gate] = [X|H] @ [Wx;Wh] (tf32 HMMA, 128x256 CTA) ----------------
__global__ void __launch_bounds__(THREADS, 1)
lstm_gemm(const float* __restrict__ X, const float* __restrict__ H,
          const float* __restrict__ Wfx, const float* __restrict__ Wfh,
          const float* __restrict__ Wix, const float* __restrict__ Wih,
          const float* __restrict__ Wox, const float* __restrict__ Woh,
          const float* __restrict__ Wcx, const float* __restrict__ Wch)
{
    extern __shared__ __align__(1024) char smem[];
    const uint32_t sbase = smem_u32(smem);
    const int tid = threadIdx.x, wid = tid >> 5, lane = tid & 31;

    // 16 consecutive CTAs share one m-tile (A reuse in L2 within a wave)
    const int nt = blockIdx.x & 15;              // 16 n-tiles of 256 across 4 gates
    const int m0 = (blockIdx.x >> 4) * BM;
    const int gate = nt >> 2;
    const int gn0 = (nt & 3) * BN;               // n offset within the gate

    const float* Wx = (gate == 0) ? Wfx : (gate == 1) ? Wix : (gate == 2) ? Wox : Wcx;
    const float* Wh = (gate == 0) ? Wfh : (gate == 1) ? Wih : (gate == 2) ? Woh : Wch;

    const int warp_m = (wid & 1) * 64;           // 2 m-positions
    const int warp_n = (wid >> 1) * 64;          // 4 n-positions

    float acc[4][8][4];
    #pragma unroll
    for (int mi = 0; mi < 4; ++mi)
        #pragma unroll
        for (int j = 0; j < 8; ++j)
            #pragma unroll
            for (int e = 0; e < 4; ++e) acc[mi][j][e] = 0.f;

    auto stage = [&](int cs, uint32_t sb) {
        const float* Asrc = (cs < 32) ? X : H;
        const float* Wsrc = (cs < 32) ? Wx : Wh;
        const int k0 = (cs & 31) * BK;
        #pragma unroll
        for (int i = 0; i < 4; ++i) {            // A: 128 rows x 32 k, sw128 rows
            const int idx = i * THREADS + tid;
            const int r = idx >> 3, c = idx & 7;
            cpasync16(sb + sw128((uint32_t)(r * 128 + c * 16)),
                      Asrc + (size_t)(m0 + r) * DIMK + k0 + c * 4);
        }
        #pragma unroll
        for (int i = 0; i < 8; ++i) {            // B: 32 k-rows x 256 n, padded stride
            const int idx = i * THREADS + tid;
            const int kr = idx >> 6, cu = idx & 63;
            cpasync16(sb + A_BYTES + (uint32_t)(kr * B_STRIDE + cu * 16),
                      Wsrc + (size_t)(k0 + kr) * DIMK + gn0 + cu * 4);
        }
    };

    stage(0, sbase);           cpcommit();
    stage(1, sbase + STG);     cpcommit();
    stage(2, sbase + 2 * STG); cpcommit();

    #pragma unroll 1
    for (int cc = 0; cc < CHUNKS; ++cc) {
        cpwait<2>();
        __syncthreads();
        if (cc + 3 < CHUNKS) stage(cc + 3, sbase + (uint32_t)((cc + 3) & 3) * STG);
        cpcommit();

        const uint32_t Ab = sbase + (uint32_t)(cc & 3) * STG;
        const uint32_t Bb = Ab + A_BYTES;

        #pragma unroll
        for (int ks = 0; ks < 4; ++ks) {
            uint32_t a[4][4];
            #pragma unroll
            for (int mi = 0; mi < 4; ++mi) {
                const uint32_t addr = Ab +
                    sw128((uint32_t)((warp_m + 16 * mi + (lane & 15)) * 128 + ks * 32 + (lane & 16)));
                ldsm4(a[mi], addr);
            }
            uint32_t b0[8], b1[8];
            #pragma unroll
            for (int j = 0; j < 8; ++j) {
                const uint32_t addr = Bb + (uint32_t)((8 * ks + (lane & 3)) * B_STRIDE
                                    + (warp_n + 8 * j + (lane >> 2)) * 4);
                b0[j] = lds32(addr);
                b1[j] = lds32(addr + 4 * B_STRIDE);
            }
            #pragma unroll
            for (int mi = 0; mi < 4; ++mi)
                #pragma unroll
                for (int j = 0; j < 8; ++j)
                    mma8(acc[mi][j], a[mi], b0[j], b1[j]);
        }
    }

    // store pre-activations
    float* zout = g_z + (size_t)gate * PLANE;
    #pragma unroll
    for (int mi = 0; mi < 4; ++mi) {
        #pragma unroll
        for (int j = 0; j < 8; ++j) {
            const int r = m0 + warp_m + 16 * mi + (lane >> 2);
            const int c = gn0 + warp_n + 8 * j + (lane & 3) * 2;
            *reinterpret_cast<float2*>(zout + (size_t)r * DIMK + c) =
                make_float2(acc[mi][j][0], acc[mi][j][1]);
            *reinterpret_cast<float2*>(zout + (size_t)(r + 8) * DIMK + c) =
                make_float2(acc[mi][j][2], acc[mi][j][3]);
        }
    }
}

// ---------------- epilogue ----------------
__global__ void __launch_bounds__(256)
lstm_epilogue(const int* __restrict__ caro,
              const float* __restrict__ bf, const float* __restrict__ bi,
              const float* __restrict__ bo, const float* __restrict__ bc,
              float* __restrict__ out)
{
    const float cf = (float)__ldg(caro);
    const size_t v = (size_t)blockIdx.x * blockDim.x + threadIdx.x;
    const int col4 = (int)(v & (DIMK / 4 - 1));

    const float4 zf = reinterpret_cast<const float4*>(g_z)[v];
    const float4 zi = reinterpret_cast<const float4*>(g_z + PLANE)[v];
    const float4 zo = reinterpret_cast<const float4*>(g_z + 2 * PLANE)[v];
    const float4 zc = reinterpret_cast<const float4*>(g_z + 3 * PLANE)[v];
    const float4 vbf = reinterpret_cast<const float4*>(bf)[col4];
    const float4 vbi = reinterpret_cast<const float4*>(bi)[col4];
    const float4 vbo = reinterpret_cast<const float4*>(bo)[col4];
    const float4 vbc = reinterpret_cast<const float4*>(bc)[col4];

    float4 h4, c4;
    const float* pzf = &zf.x; const float* pzi = &zi.x;
    const float* pzo = &zo.x; const float* pzc = &zc.x;
    const float* pbf = &vbf.x; const float* pbi = &vbi.x;
    const float* pbo = &vbo.x; const float* pbc = &vbc.x;
    float* ph = &h4.x; float* pc = &c4.x;
    #pragma unroll
    for (int e = 0; e < 4; ++e) {
        const float f  = 1.f / (1.f + expf(-(pzf[e] + pbf[e])));
        const float ii = 1.f / (1.f + expf(-(pzi[e] + pbi[e])));
        const float oo = 1.f / (1.f + expf(-(pzo[e] + pbo[e])));
        const float gg = tanhf(pzc[e] + pbc[e]);
        const float cv = f * cf + ii * gg;
        pc[e] = cv;
        ph[e] = oo * cv;
    }
    reinterpret_cast<float4*>(out)[v] = h4;
    reinterpret_cast<float4*>(out + PLANE)[v] = c4;
}

// ---------------- launch ----------------
extern "C" void kernel_launch(void* const* d_in, const int* in_sizes, int n_in,
                              void* d_out, int out_size) {
    (void)in_sizes; (void)n_in; (void)out_size;
    const float* X    = (const float*)d_in[0];
    const float* H    = (const float*)d_in[1];
    const int*   caro = (const int*)d_in[2];
    const float* Wfx = (const float*)d_in[3];
    const float* Wfh = (const float*)d_in[4];
    const float* bf  = (const float*)d_in[5];
    const float* Wix = (const float*)d_in[6];
    const float* Wih = (const float*)d_in[7];
    const float* bi  = (const float*)d_in[8];
    const float* Wox = (const float*)d_in[9];
    const float* Woh = (const float*)d_in[10];
    const float* bo  = (const float*)d_in[11];
    const float* Wcx = (const float*)d_in[12];
    const float* Wch = (const float*)d_in[13];
    const float* bc  = (const float*)d_in[14];
    float* out = (float*)d_out;

    cudaFuncSetAttribute(lstm_gemm, cudaFuncAttributeMaxDynamicSharedMemorySize, SMEM_TOTAL);

    const int grid_gemm = (BATCH / BM) * 16;     // 128 m-tiles * 16 n-tiles = 2048
    lstm_gemm<<<grid_gemm, THREADS, SMEM_TOTAL>>>(X, H, Wfx, Wfh, Wix, Wih, Wox, Woh, Wcx, Wch);

    lstm_epilogue<<<(int)(PLANE / 4 / 256), 256>>>(caro, bf, bi, bo, bc, out);
}

// round 6
// speedup vs baseline: 6.6891x; 1.7679x over previous
#include <cuda_runtime.h>
#include <cuda_fp16.h>
#include <cstdint>
#include <cstddef>

#define DI __device__ __forceinline__

// ---------------- constants ----------------
constexpr int BM = 128, BN = 128, THREADS = 256;
constexpr int DIMK = 1024;
constexpr int BATCH = 16384;
constexpr int KTOT = 2048;
constexpr int CHUNKS = 64;                        // BK=32 halves per chunk
constexpr size_t PLANE = (size_t)BATCH * DIMK;

// padded-stride smem tiles (fp16), conflict-free for ldmatrix (stride mod 128 spans 8 units)
constexpr uint32_t A_STRIDE = 80;                 // 64B data + 16B pad
constexpr uint32_t A_BYTES  = 128 * A_STRIDE;     // 10240
constexpr uint32_t B_STRIDE = 272;                // 256B data + 16B pad
constexpr uint32_t B_BYTES  = 32 * B_STRIDE;      // 8704
constexpr uint32_t STG = A_BYTES + B_BYTES;       // 18944
constexpr uint32_t SMEM_TOTAL = 4 * STG;          // 75776 -> 2 CTAs/SM

// ---------------- device scratch ----------------
__device__ __half g_XH[(size_t)BATCH * KTOT];     // [m][k]: X cols 0..1023 | H cols 1024..2047
__device__ __half g_W[(size_t)4 * KTOT * DIMK];   // [gate][k][n], k = [Wx rows | Wh rows]
__device__ float  g_z[4 * PLANE];                 // pre-activations

// ---------------- PTX helpers ----------------
DI uint32_t smem_u32(const void* p) {
    uint32_t a;
    asm("{ .reg .u64 t; cvta.to.shared.u64 t, %1; cvt.u32.u64 %0, t; }" : "=r"(a) : "l"(p));
    return a;
}
DI void cpasync16(uint32_t dst, const void* src) {
    asm volatile("cp.async.cg.shared.global [%0], [%1], 16;" :: "r"(dst), "l"(src) : "memory");
}
DI void cpcommit() { asm volatile("cp.async.commit_group;" ::: "memory"); }
template<int N> DI void cpwait() { asm volatile("cp.async.wait_group %0;" :: "n"(N) : "memory"); }
DI void ldsm4(uint32_t* r, uint32_t a) {
    asm volatile("ldmatrix.sync.aligned.m8n8.x4.shared.b16 {%0,%1,%2,%3}, [%4];"
                 : "=r"(r[0]), "=r"(r[1]), "=r"(r[2]), "=r"(r[3]) : "r"(a));
}
DI void ldsm4t(uint32_t* r, uint32_t a) {
    asm volatile("ldmatrix.sync.aligned.m8n8.x4.trans.shared.b16 {%0,%1,%2,%3}, [%4];"
                 : "=r"(r[0]), "=r"(r[1]), "=r"(r[2]), "=r"(r[3]) : "r"(a));
}
DI void mma16(float* d, const uint32_t* a, uint32_t b0, uint32_t b1) {
    asm volatile(
        "mma.sync.aligned.m16n8k16.row.col.f32.f16.f16.f32 "
        "{%0,%1,%2,%3},{%4,%5,%6,%7},{%8,%9},{%0,%1,%2,%3};"
        : "+f"(d[0]), "+f"(d[1]), "+f"(d[2]), "+f"(d[3])
        : "r"(a[0]), "r"(a[1]), "r"(a[2]), "r"(a[3]), "r"(b0), "r"(b1));
}

// ---------------- prep: fp16 conversion ----------------
__global__ void __launch_bounds__(256)
convXH(const float* __restrict__ X, const float* __restrict__ H)
{
    const int m = blockIdx.x, t = threadIdx.x;
    const float* src = (t < 128) ? X + (size_t)m * 1024 + 8 * t
                                 : H + (size_t)m * 1024 + 8 * (t - 128);
    const float4 v0 = reinterpret_cast<const float4*>(src)[0];
    const float4 v1 = reinterpret_cast<const float4*>(src)[1];
    __half2 h[4];
    h[0] = __floats2half2_rn(v0.x, v0.y);
    h[1] = __floats2half2_rn(v0.z, v0.w);
    h[2] = __floats2half2_rn(v1.x, v1.y);
    h[3] = __floats2half2_rn(v1.z, v1.w);
    *reinterpret_cast<uint4*>(g_XH + (size_t)m * KTOT + 8 * t) = *reinterpret_cast<uint4*>(h);
}

__global__ void __launch_bounds__(128)
convW(const float* __restrict__ Wfx, const float* __restrict__ Wfh,
      const float* __restrict__ Wix, const float* __restrict__ Wih,
      const float* __restrict__ Wox, const float* __restrict__ Woh,
      const float* __restrict__ Wcx, const float* __restrict__ Wch)
{
    const int gate = blockIdx.x >> 11;
    const int k = blockIdx.x & 2047;
    const int t = threadIdx.x;
    const float* Wx = (gate == 0) ? Wfx : (gate == 1) ? Wix : (gate == 2) ? Wox : Wcx;
    const float* Wh = (gate == 0) ? Wfh : (gate == 1) ? Wih : (gate == 2) ? Woh : Wch;
    const float* src = ((k < 1024) ? Wx + (size_t)k * 1024 : Wh + (size_t)(k - 1024) * 1024) + 8 * t;
    const float4 v0 = reinterpret_cast<const float4*>(src)[0];
    const float4 v1 = reinterpret_cast<const float4*>(src)[1];
    __half2 h[4];
    h[0] = __floats2half2_rn(v0.x, v0.y);
    h[1] = __floats2half2_rn(v0.z, v0.w);
    h[2] = __floats2half2_rn(v1.x, v1.y);
    h[3] = __floats2half2_rn(v1.z, v1.w);
    *reinterpret_cast<uint4*>(g_W + ((size_t)gate * KTOT + k) * DIMK + 8 * t) =
        *reinterpret_cast<uint4*>(h);
}

// ---------------- GEMM: z[gate] = [X|H]h @ Wh (fp16 HMMA k16, fp32 accum) ----------------
__global__ void __launch_bounds__(THREADS, 2)
lstm_gemm_h(void)
{
    extern __shared__ __align__(1024) char smem[];
    const uint32_t sbase = smem_u32(smem);
    const int tid = threadIdx.x, wid = tid >> 5, lane = tid & 31;

    // 32 consecutive CTAs share one m-tile; W (16MB fp16) stays L2-resident per wave
    const int nt = blockIdx.x & 31;              // 8 n-tiles x 4 gates
    const int m0 = (blockIdx.x >> 5) * BM;
    const int gate = nt >> 3;
    const int n0 = (nt & 7) * BN;

    const int warp_m = (wid & 1) * 64;
    const int warp_n = (wid >> 1) * 32;

    float acc[4][4][4];
    #pragma unroll
    for (int mi = 0; mi < 4; ++mi)
        #pragma unroll
        for (int j = 0; j < 4; ++j)
            #pragma unroll
            for (int e = 0; e < 4; ++e) acc[mi][j][e] = 0.f;

    auto stage = [&](int cs, uint32_t sb) {
        const int k0 = cs * 32;
        // A: 128 rows x 32 halves (64B = 4 x 16B), stride 80
        #pragma unroll
        for (int i = 0; i < 2; ++i) {
            const int idx = i * THREADS + tid;
            const int r = idx >> 2, c = idx & 3;
            cpasync16(sb + (uint32_t)(r * A_STRIDE + c * 16),
                      g_XH + (size_t)(m0 + r) * KTOT + k0 + c * 8);
        }
        // B: 32 k-rows x 128 halves (256B = 16 x 16B), stride 272
        #pragma unroll
        for (int i = 0; i < 2; ++i) {
            const int idx = i * THREADS + tid;
            const int r = idx >> 4, c = idx & 15;
            cpasync16(sb + A_BYTES + (uint32_t)(r * B_STRIDE + c * 16),
                      g_W + ((size_t)gate * KTOT + k0 + r) * DIMK + n0 + c * 8);
        }
    };

    stage(0, sbase);           cpcommit();
    stage(1, sbase + STG);     cpcommit();
    stage(2, sbase + 2 * STG); cpcommit();

    #pragma unroll 1
    for (int cc = 0; cc < CHUNKS; ++cc) {
        cpwait<2>();
        __syncthreads();
        if (cc + 3 < CHUNKS) stage(cc + 3, sbase + (uint32_t)((cc + 3) & 3) * STG);
        cpcommit();

        const uint32_t Ab = sbase + (uint32_t)(cc & 3) * STG;
        const uint32_t Bb = Ab + A_BYTES;

        #pragma unroll
        for (int ks = 0; ks < 2; ++ks) {         // two k16 steps per 32-half chunk
            uint32_t a[4][4];
            #pragma unroll
            for (int mi = 0; mi < 4; ++mi)
                ldsm4(a[mi], Ab + (uint32_t)((warp_m + 16 * mi + (lane & 15)) * A_STRIDE
                                              + ks * 32 + ((lane >> 4) << 4)));
            uint32_t b[2][4];                     // [nblk16][j0b0,j0b1,j1b0,j1b1]
            #pragma unroll
            for (int nb = 0; nb < 2; ++nb)
                ldsm4t(b[nb], Bb + (uint32_t)((ks * 16 + (lane & 15)) * B_STRIDE
                                               + (warp_n + nb * 16 + ((lane >> 4) << 3)) * 2));
            #pragma unroll
            for (int mi = 0; mi < 4; ++mi)
                #pragma unroll
                for (int j = 0; j < 4; ++j)
                    mma16(acc[mi][j], a[mi], b[j >> 1][(j & 1) * 2], b[j >> 1][(j & 1) * 2 + 1]);
        }
    }

    float* zout = g_z + (size_t)gate * PLANE;
    #pragma unroll
    for (int mi = 0; mi < 4; ++mi) {
        #pragma unroll
        for (int j = 0; j < 4; ++j) {
            const int r = m0 + warp_m + 16 * mi + (lane >> 2);
            const int c = n0 + warp_n + 8 * j + (lane & 3) * 2;
            *reinterpret_cast<float2*>(zout + (size_t)r * DIMK + c) =
                make_float2(acc[mi][j][0], acc[mi][j][1]);
            *reinterpret_cast<float2*>(zout + (size_t)(r + 8) * DIMK + c) =
                make_float2(acc[mi][j][2], acc[mi][j][3]);
        }
    }
}

// ---------------- epilogue ----------------
__global__ void __launch_bounds__(256)
lstm_epilogue(const int* __restrict__ caro,
              const float* __restrict__ bf, const float* __restrict__ bi,
              const float* __restrict__ bo, const float* __restrict__ bc,
              float* __restrict__ out)
{
    const float cf = (float)__ldg(caro);
    const size_t v = (size_t)blockIdx.x * blockDim.x + threadIdx.x;
    const int col4 = (int)(v & (DIMK / 4 - 1));

    const float4 zf = reinterpret_cast<const float4*>(g_z)[v];
    const float4 zi = reinterpret_cast<const float4*>(g_z + PLANE)[v];
    const float4 zo = reinterpret_cast<const float4*>(g_z + 2 * PLANE)[v];
    const float4 zc = reinterpret_cast<const float4*>(g_z + 3 * PLANE)[v];
    const float4 vbf = reinterpret_cast<const float4*>(bf)[col4];
    const float4 vbi = reinterpret_cast<const float4*>(bi)[col4];
    const float4 vbo = reinterpret_cast<const float4*>(bo)[col4];
    const float4 vbc = reinterpret_cast<const float4*>(bc)[col4];

    float4 h4, c4;
    const float* pzf = &zf.x; const float* pzi = &zi.x;
    const float* pzo = &zo.x; const float* pzc = &zc.x;
    const float* pbf = &vbf.x; const float* pbi = &vbi.x;
    const float* pbo = &vbo.x; const float* pbc = &vbc.x;
    float* ph = &h4.x; float* pc = &c4.x;
    #pragma unroll
    for (int e = 0; e < 4; ++e) {
        const float f  = 1.f / (1.f + expf(-(pzf[e] + pbf[e])));
        const float ii = 1.f / (1.f + expf(-(pzi[e] + pbi[e])));
        const float oo = 1.f / (1.f + expf(-(pzo[e] + pbo[e])));
        const float gg = tanhf(pzc[e] + pbc[e]);
        const float cv = f * cf + ii * gg;
        pc[e] = cv;
        ph[e] = oo * cv;
    }
    reinterpret_cast<float4*>(out)[v] = h4;
    reinterpret_cast<float4*>(out + PLANE)[v] = c4;
}

// ---------------- launch ----------------
extern "C" void kernel_launch(void* const* d_in, const int* in_sizes, int n_in,
                              void* d_out, int out_size) {
    (void)in_sizes; (void)n_in; (void)out_size;
    const float* X    = (const float*)d_in[0];
    const float* H    = (const float*)d_in[1];
    const int*   caro = (const int*)d_in[2];
    const float* Wfx = (const float*)d_in[3];
    const float* Wfh = (const float*)d_in[4];
    const float* bf  = (const float*)d_in[5];
    const float* Wix = (const float*)d_in[6];
    const float* Wih = (const float*)d_in[7];
    const float* bi  = (const float*)d_in[8];
    const float* Wox = (const float*)d_in[9];
    const float* Woh = (const float*)d_in[10];
    const float* bo  = (const float*)d_in[11];
    const float* Wcx = (const float*)d_in[12];
    const float* Wch = (const float*)d_in[13];
    const float* bc  = (const float*)d_in[14];
    float* out = (float*)d_out;

    cudaFuncSetAttribute(lstm_gemm_h, cudaFuncAttributeMaxDynamicSharedMemorySize, SMEM_TOTAL);

    convXH<<<BATCH, 256>>>(X, H);
    convW<<<4 * KTOT, 128>>>(Wfx, Wfh, Wix, Wih, Wox, Woh, Wcx, Wch);
    lstm_gemm_h<<<(BATCH / BM) * 32, THREADS, SMEM_TOTAL>>>();
    lstm_epilogue<<<(int)(PLANE / 4 / 256), 256>>>(caro, bf, bi, bo, bc, out);
}

// round 7
// speedup vs baseline: 6.9777x; 1.0431x over previous
#include <cuda_runtime.h>
#include <cuda_fp16.h>
#include <cstdint>
#include <cstddef>

#define DI __device__ __forceinline__

// ---------------- constants ----------------
constexpr int BM = 128, BN = 128, BK = 64, THREADS = 256;
constexpr int DIMK = 1024;
constexpr int BATCH = 16384;
constexpr int KTOT = 2048;
constexpr int CHUNKS = 32;                        // 2048 / 64
constexpr size_t PLANE = (size_t)BATCH * DIMK;

// padded-stride fp16 smem tiles: stride mod 128 = 16 -> 8 consecutive rows hit
// 8 distinct 16B units => conflict-free ldmatrix without swizzle
constexpr uint32_t A_STRIDE = 144;                // 128B data + 16B pad
constexpr uint32_t A_BYTES  = 128 * A_STRIDE;     // 18432
constexpr uint32_t B_STRIDE = 272;                // 256B data + 16B pad
constexpr uint32_t B_BYTES  = 64 * B_STRIDE;      // 17408
constexpr uint32_t STG = A_BYTES + B_BYTES;       // 35840
constexpr uint32_t SMEM_TOTAL = 3 * STG;          // 107520 -> 2 CTAs/SM (215KB < 228KB)

// ---------------- device scratch ----------------
__device__ __half g_XH[(size_t)BATCH * KTOT];     // [m][k]: X | H
__device__ __half g_W[(size_t)4 * KTOT * DIMK];   // [gate][k][n]
__device__ float  g_z[4 * PLANE];                 // pre-activations

// ---------------- PTX helpers ----------------
DI uint32_t smem_u32(const void* p) {
    uint32_t a;
    asm("{ .reg .u64 t; cvta.to.shared.u64 t, %1; cvt.u32.u64 %0, t; }" : "=r"(a) : "l"(p));
    return a;
}
DI void cpasync16(uint32_t dst, const void* src) {
    asm volatile("cp.async.cg.shared.global [%0], [%1], 16;" :: "r"(dst), "l"(src) : "memory");
}
DI void cpcommit() { asm volatile("cp.async.commit_group;" ::: "memory"); }
template<int N> DI void cpwait() { asm volatile("cp.async.wait_group %0;" :: "n"(N) : "memory"); }
DI void ldsm4(uint32_t* r, uint32_t a) {
    asm volatile("ldmatrix.sync.aligned.m8n8.x4.shared.b16 {%0,%1,%2,%3}, [%4];"
                 : "=r"(r[0]), "=r"(r[1]), "=r"(r[2]), "=r"(r[3]) : "r"(a));
}
DI void ldsm4t(uint32_t* r, uint32_t a) {
    asm volatile("ldmatrix.sync.aligned.m8n8.x4.trans.shared.b16 {%0,%1,%2,%3}, [%4];"
                 : "=r"(r[0]), "=r"(r[1]), "=r"(r[2]), "=r"(r[3]) : "r"(a));
}
DI void mma16(float* d, const uint32_t* a, uint32_t b0, uint32_t b1) {
    asm volatile(
        "mma.sync.aligned.m16n8k16.row.col.f32.f16.f16.f32 "
        "{%0,%1,%2,%3},{%4,%5,%6,%7},{%8,%9},{%0,%1,%2,%3};"
        : "+f"(d[0]), "+f"(d[1]), "+f"(d[2]), "+f"(d[3])
        : "r"(a[0]), "r"(a[1]), "r"(a[2]), "r"(a[3]), "r"(b0), "r"(b1));
}

// ---------------- prep: fp16 conversion ----------------
__global__ void __launch_bounds__(256)
convXH(const float* __restrict__ X, const float* __restrict__ H)
{
    const int m = blockIdx.x, t = threadIdx.x;
    const float* src = (t < 128) ? X + (size_t)m * 1024 + 8 * t
                                 : H + (size_t)m * 1024 + 8 * (t - 128);
    const float4 v0 = reinterpret_cast<const float4*>(src)[0];
    const float4 v1 = reinterpret_cast<const float4*>(src)[1];
    __half2 h[4];
    h[0] = __floats2half2_rn(v0.x, v0.y);
    h[1] = __floats2half2_rn(v0.z, v0.w);
    h[2] = __floats2half2_rn(v1.x, v1.y);
    h[3] = __floats2half2_rn(v1.z, v1.w);
    *reinterpret_cast<uint4*>(g_XH + (size_t)m * KTOT + 8 * t) = *reinterpret_cast<uint4*>(h);
}

__global__ void __launch_bounds__(128)
convW(const float* __restrict__ Wfx, const float* __restrict__ Wfh,
      const float* __restrict__ Wix, const float* __restrict__ Wih,
      const float* __restrict__ Wox, const float* __restrict__ Woh,
      const float* __restrict__ Wcx, const float* __restrict__ Wch)
{
    const int gate = blockIdx.x >> 11;
    const int k = blockIdx.x & 2047;
    const int t = threadIdx.x;
    const float* Wx = (gate == 0) ? Wfx : (gate == 1) ? Wix : (gate == 2) ? Wox : Wcx;
    const float* Wh = (gate == 0) ? Wfh : (gate == 1) ? Wih : (gate == 2) ? Woh : Wch;
    const float* src = ((k < 1024) ? Wx + (size_t)k * 1024 : Wh + (size_t)(k - 1024) * 1024) + 8 * t;
    const float4 v0 = reinterpret_cast<const float4*>(src)[0];
    const float4 v1 = reinterpret_cast<const float4*>(src)[1];
    __half2 h[4];
    h[0] = __floats2half2_rn(v0.x, v0.y);
    h[1] = __floats2half2_rn(v0.z, v0.w);
    h[2] = __floats2half2_rn(v1.x, v1.y);
    h[3] = __floats2half2_rn(v1.z, v1.w);
    *reinterpret_cast<uint4*>(g_W + ((size_t)gate * KTOT + k) * DIMK + 8 * t) =
        *reinterpret_cast<uint4*>(h);
}

// ---------------- GEMM: z[gate] = [X|H]h @ Wh (fp16 HMMA k16, fp32 accum) ----------------
__global__ void __launch_bounds__(THREADS, 2)
lstm_gemm_h(void)
{
    extern __shared__ __align__(1024) char smem[];
    const uint32_t sbase = smem_u32(smem);
    const int tid = threadIdx.x, wid = tid >> 5, lane = tid & 31;

    // 32 consecutive CTAs share one m-tile; W (16.8MB fp16) is L2-resident
    const int nt = blockIdx.x & 31;
    const int m0 = (blockIdx.x >> 5) * BM;
    const int gate = nt >> 3;
    const int n0 = (nt & 7) * BN;

    const int warp_m = (wid & 1) * 64;
    const int warp_n = (wid >> 1) * 32;

    float acc[4][4][4];
    #pragma unroll
    for (int mi = 0; mi < 4; ++mi)
        #pragma unroll
        for (int j = 0; j < 4; ++j)
            #pragma unroll
            for (int e = 0; e < 4; ++e) acc[mi][j][e] = 0.f;

    auto stage = [&](int cs, uint32_t sb) {
        const int k0 = cs * BK;
        // A: 128 rows x 64 halves (128B = 8 x 16B per row), stride 144
        #pragma unroll
        for (int i = 0; i < 4; ++i) {
            const int idx = i * THREADS + tid;
            const int r = idx >> 3, c = idx & 7;
            cpasync16(sb + (uint32_t)(r * A_STRIDE + c * 16),
                      g_XH + (size_t)(m0 + r) * KTOT + k0 + c * 8);
        }
        // B: 64 k-rows x 128 halves (256B = 16 x 16B per row), stride 272
        #pragma unroll
        for (int i = 0; i < 4; ++i) {
            const int idx = i * THREADS + tid;
            const int r = idx >> 4, c = idx & 15;
            cpasync16(sb + A_BYTES + (uint32_t)(r * B_STRIDE + c * 16),
                      g_W + ((size_t)gate * KTOT + k0 + r) * DIMK + n0 + c * 8);
        }
    };

    stage(0, sbase);        cpcommit();
    stage(1, sbase + STG);  cpcommit();

    #pragma unroll 1
    for (int cc = 0; cc < CHUNKS; ++cc) {
        cpwait<1>();
        __syncthreads();
        if (cc + 2 < CHUNKS) {
            static const uint32_t off3[3] = {0, STG, 2 * STG};
            stage(cc + 2, sbase + off3[(cc + 2) % 3]);
        }
        cpcommit();

        const uint32_t Ab = sbase + (uint32_t)((cc % 3) * STG);
        const uint32_t Bb = Ab + A_BYTES;

        #pragma unroll
        for (int ks = 0; ks < 4; ++ks) {          // four k16 steps per 64-half chunk
            uint32_t a[4][4];
            #pragma unroll
            for (int mi = 0; mi < 4; ++mi)
                ldsm4(a[mi], Ab + (uint32_t)((warp_m + 16 * mi + (lane & 15)) * A_STRIDE
                                              + ks * 32 + ((lane >> 4) << 4)));
            uint32_t b[2][4];
            #pragma unroll
            for (int nb = 0; nb < 2; ++nb)
                ldsm4t(b[nb], Bb + (uint32_t)((ks * 16 + (lane & 15)) * B_STRIDE
                                               + (warp_n + nb * 16 + ((lane >> 4) << 3)) * 2));
            #pragma unroll
            for (int mi = 0; mi < 4; ++mi)
                #pragma unroll
                for (int j = 0; j < 4; ++j)
                    mma16(acc[mi][j], a[mi], b[j >> 1][(j & 1) * 2], b[j >> 1][(j & 1) * 2 + 1]);
        }
    }

    float* zout = g_z + (size_t)gate * PLANE;
    #pragma unroll
    for (int mi = 0; mi < 4; ++mi) {
        #pragma unroll
        for (int j = 0; j < 4; ++j) {
            const int r = m0 + warp_m + 16 * mi + (lane >> 2);
            const int c = n0 + warp_n + 8 * j + (lane & 3) * 2;
            *reinterpret_cast<float2*>(zout + (size_t)r * DIMK + c) =
                make_float2(acc[mi][j][0], acc[mi][j][1]);
            *reinterpret_cast<float2*>(zout + (size_t)(r + 8) * DIMK + c) =
                make_float2(acc[mi][j][2], acc[mi][j][3]);
        }
    }
}

// ---------------- epilogue ----------------
__global__ void __launch_bounds__(256)
lstm_epilogue(const int* __restrict__ caro,
              const float* __restrict__ bf, const float* __restrict__ bi,
              const float* __restrict__ bo, const float* __restrict__ bc,
              float* __restrict__ out)
{
    const float cf = (float)__ldg(caro);
    const size_t v = (size_t)blockIdx.x * blockDim.x + threadIdx.x;
    const int col4 = (int)(v & (DIMK / 4 - 1));

    const float4 zf = reinterpret_cast<const float4*>(g_z)[v];
    const float4 zi = reinterpret_cast<const float4*>(g_z + PLANE)[v];
    const float4 zo = reinterpret_cast<const float4*>(g_z + 2 * PLANE)[v];
    const float4 zc = reinterpret_cast<const float4*>(g_z + 3 * PLANE)[v];
    const float4 vbf = reinterpret_cast<const float4*>(bf)[col4];
    const float4 vbi = reinterpret_cast<const float4*>(bi)[col4];
    const float4 vbo = reinterpret_cast<const float4*>(bo)[col4];
    const float4 vbc = reinterpret_cast<const float4*>(bc)[col4];

    float4 h4, c4;
    const float* pzf = &zf.x; const float* pzi = &zi.x;
    const float* pzo = &zo.x; const float* pzc = &zc.x;
    const float* pbf = &vbf.x; const float* pbi = &vbi.x;
    const float* pbo = &vbo.x; const float* pbc = &vbc.x;
    float* ph = &h4.x; float* pc = &c4.x;
    #pragma unroll
    for (int e = 0; e < 4; ++e) {
        const float f  = 1.f / (1.f + expf(-(pzf[e] + pbf[e])));
        const float ii = 1.f / (1.f + expf(-(pzi[e] + pbi[e])));
        const float oo = 1.f / (1.f + expf(-(pzo[e] + pbo[e])));
        const float gg = tanhf(pzc[e] + pbc[e]);
        const float cv = f * cf + ii * gg;
        pc[e] = cv;
        ph[e] = oo * cv;
    }
    reinterpret_cast<float4*>(out)[v] = h4;
    reinterpret_cast<float4*>(out + PLANE)[v] = c4;
}

// ---------------- launch ----------------
extern "C" void kernel_launch(void* const* d_in, const int* in_sizes, int n_in,
                              void* d_out, int out_size) {
    (void)in_sizes; (void)n_in; (void)out_size;
    const float* X    = (const float*)d_in[0];
    const float* H    = (const float*)d_in[1];
    const int*   caro = (const int*)d_in[2];
    const float* Wfx = (const float*)d_in[3];
    const float* Wfh = (const float*)d_in[4];
    const float* bf  = (const float*)d_in[5];
    const float* Wix = (const float*)d_in[6];
    const float* Wih = (const float*)d_in[7];
    const float* bi  = (const float*)d_in[8];
    const float* Wox = (const float*)d_in[9];
    const float* Woh = (const float*)d_in[10];
    const float* bo  = (const float*)d_in[11];
    const float* Wcx = (const float*)d_in[12];
    const float* Wch = (const float*)d_in[13];
    const float* bc  = (const float*)d_in[14];
    float* out = (float*)d_out;

    cudaFuncSetAttribute(lstm_gemm_h, cudaFuncAttributeMaxDynamicSharedMemorySize, SMEM_TOTAL);

    convXH<<<BATCH, 256>>>(X, H);
    convW<<<4 * KTOT, 128>>>(Wfx, Wfh, Wix, Wih, Wox, Woh, Wcx, Wch);
    lstm_gemm_h<<<(BATCH / BM) * 32, THREADS, SMEM_TOTAL>>>();
    lstm_epilogue<<<(int)(PLANE / 4 / 256), 256>>>(caro, bf, bi, bo, bc, out);
}

// round 8
// speedup vs baseline: 7.2501x; 1.0390x over previous
#include <cuda_runtime.h>
#include <cuda_fp16.h>
#include <cstdint>
#include <cstddef>

#define DI __device__ __forceinline__

// ---------------- constants ----------------
constexpr int BM = 128, BN = 32, BK = 64, THREADS = 256;
constexpr int DIMK = 1024;
constexpr int BATCH = 16384;
constexpr int KTOT = 2048;
constexpr int CHUNKS = 32;                        // 2048 / 64
constexpr size_t PLANE = (size_t)BATCH * DIMK;

// A: sw128-swizzled rows of 128B (64 halves). B: 4 gate tiles, 64k x 32n, stride 80.
constexpr uint32_t A_BYTES  = 128 * 128;          // 16384
constexpr uint32_t BG_STRIDE = 80;                // 64B data + 16B pad (rows mod 8 units: perm)
constexpr uint32_t BG_BYTES  = 64 * BG_STRIDE;    // 5120 per gate
constexpr uint32_t B_BYTES   = 4 * BG_BYTES;      // 20480
constexpr uint32_t STG = A_BYTES + B_BYTES;       // 36864
constexpr uint32_t SMEM_TOTAL = 3 * STG;          // 110592 -> 2 CTAs/SM (216KB)

// z-exchange layout in reused smem: [gate][128][36] floats
constexpr uint32_t ZS_G = 128 * 36;

// ---------------- device scratch ----------------
__device__ __half g_XH[(size_t)BATCH * KTOT];     // [m][k]: X | H
__device__ __half g_W[(size_t)4 * KTOT * DIMK];   // [gate][k][n]

// ---------------- PTX helpers ----------------
DI uint32_t smem_u32(const void* p) {
    uint32_t a;
    asm("{ .reg .u64 t; cvta.to.shared.u64 t, %1; cvt.u32.u64 %0, t; }" : "=r"(a) : "l"(p));
    return a;
}
DI uint32_t sw128(uint32_t o) { return o ^ ((o >> 3) & 0x70); }
DI void cpasync16(uint32_t dst, const void* src) {
    asm volatile("cp.async.cg.shared.global [%0], [%1], 16;" :: "r"(dst), "l"(src) : "memory");
}
DI void cpcommit() { asm volatile("cp.async.commit_group;" ::: "memory"); }
template<int N> DI void cpwait() { asm volatile("cp.async.wait_group %0;" :: "n"(N) : "memory"); }
DI void ldsm4(uint32_t* r, uint32_t a) {
    asm volatile("ldmatrix.sync.aligned.m8n8.x4.shared.b16 {%0,%1,%2,%3}, [%4];"
                 : "=r"(r[0]), "=r"(r[1]), "=r"(r[2]), "=r"(r[3]) : "r"(a));
}
DI void ldsm4t(uint32_t* r, uint32_t a) {
    asm volatile("ldmatrix.sync.aligned.m8n8.x4.trans.shared.b16 {%0,%1,%2,%3}, [%4];"
                 : "=r"(r[0]), "=r"(r[1]), "=r"(r[2]), "=r"(r[3]) : "r"(a));
}
DI void mma16(float* d, const uint32_t* a, uint32_t b0, uint32_t b1) {
    asm volatile(
        "mma.sync.aligned.m16n8k16.row.col.f32.f16.f16.f32 "
        "{%0,%1,%2,%3},{%4,%5,%6,%7},{%8,%9},{%0,%1,%2,%3};"
        : "+f"(d[0]), "+f"(d[1]), "+f"(d[2]), "+f"(d[3])
        : "r"(a[0]), "r"(a[1]), "r"(a[2]), "r"(a[3]), "r"(b0), "r"(b1));
}

// ---------------- prep: fp16 conversion ----------------
__global__ void __launch_bounds__(256)
convXH(const float* __restrict__ X, const float* __restrict__ H)
{
    const int m = blockIdx.x, t = threadIdx.x;
    const float* src = (t < 128) ? X + (size_t)m * 1024 + 8 * t
                                 : H + (size_t)m * 1024 + 8 * (t - 128);
    const float4 v0 = reinterpret_cast<const float4*>(src)[0];
    const float4 v1 = reinterpret_cast<const float4*>(src)[1];
    __half2 h[4];
    h[0] = __floats2half2_rn(v0.x, v0.y);
    h[1] = __floats2half2_rn(v0.z, v0.w);
    h[2] = __floats2half2_rn(v1.x, v1.y);
    h[3] = __floats2half2_rn(v1.z, v1.w);
    *reinterpret_cast<uint4*>(g_XH + (size_t)m * KTOT + 8 * t) = *reinterpret_cast<uint4*>(h);
}

__global__ void __launch_bounds__(128)
convW(const float* __restrict__ Wfx, const float* __restrict__ Wfh,
      const float* __restrict__ Wix, const float* __restrict__ Wih,
      const float* __restrict__ Wox, const float* __restrict__ Woh,
      const float* __restrict__ Wcx, const float* __restrict__ Wch)
{
    const int gate = blockIdx.x >> 11;
    const int k = blockIdx.x & 2047;
    const int t = threadIdx.x;
    const float* Wx = (gate == 0) ? Wfx : (gate == 1) ? Wix : (gate == 2) ? Wox : Wcx;
    const float* Wh = (gate == 0) ? Wfh : (gate == 1) ? Wih : (gate == 2) ? Woh : Wch;
    const float* src = ((k < 1024) ? Wx + (size_t)k * 1024 : Wh + (size_t)(k - 1024) * 1024) + 8 * t;
    const float4 v0 = reinterpret_cast<const float4*>(src)[0];
    const float4 v1 = reinterpret_cast<const float4*>(src)[1];
    __half2 h[4];
    h[0] = __floats2half2_rn(v0.x, v0.y);
    h[1] = __floats2half2_rn(v0.z, v0.w);
    h[2] = __floats2half2_rn(v1.x, v1.y);
    h[3] = __floats2half2_rn(v1.z, v1.w);
    *reinterpret_cast<uint4*>(g_W + ((size_t)gate * KTOT + k) * DIMK + 8 * t) =
        *reinterpret_cast<uint4*>(h);
}

// ---------------- fused GEMM + LSTM cell ----------------
__global__ void __launch_bounds__(THREADS, 2)
lstm_fused(const int* __restrict__ caro,
           const float* __restrict__ bf, const float* __restrict__ bi,
           const float* __restrict__ bo, const float* __restrict__ bc,
           float* __restrict__ out)
{
    extern __shared__ __align__(1024) char smem[];
    const uint32_t sbase = smem_u32(smem);
    const int tid = threadIdx.x, wid = tid >> 5, lane = tid & 31;

    // 32 n-tiles of 32 cols per m-tile; all CTAs of an m-tile share A in L2
    const int n0 = (blockIdx.x & 31) * BN;
    const int m0 = (blockIdx.x >> 5) * BM;

    const int gate   = wid >> 1;                  // warp -> gate
    const int warp_m = (wid & 1) * 64;            // warp -> m half

    float acc[4][4][4];
    #pragma unroll
    for (int mi = 0; mi < 4; ++mi)
        #pragma unroll
        for (int j = 0; j < 4; ++j)
            #pragma unroll
            for (int e = 0; e < 4; ++e) acc[mi][j][e] = 0.f;

    auto stage = [&](int cs, uint32_t sb) {
        const int k0 = cs * BK;
        // A: 128 rows x 64 halves, sw128 swizzled 128B rows (1024 units)
        #pragma unroll
        for (int i = 0; i < 4; ++i) {
            const int idx = i * THREADS + tid;
            const int r = idx >> 3, c = idx & 7;
            cpasync16(sb + sw128((uint32_t)(r * 128 + c * 16)),
                      g_XH + (size_t)(m0 + r) * KTOT + k0 + c * 8);
        }
        // B: 4 gates x 64 k-rows x 32 halves (4 units/row), stride 80 (1024 units)
        #pragma unroll
        for (int i = 0; i < 4; ++i) {
            const int idx = i * THREADS + tid;
            const int g = idx >> 8, u = idx & 255;
            const int r = u >> 2, c = u & 3;
            cpasync16(sb + A_BYTES + (uint32_t)g * BG_BYTES + (uint32_t)(r * BG_STRIDE + c * 16),
                      g_W + ((size_t)g * KTOT + k0 + r) * DIMK + n0 + c * 8);
        }
    };

    stage(0, sbase);        cpcommit();
    stage(1, sbase + STG);  cpcommit();

    #pragma unroll 1
    for (int cc = 0; cc < CHUNKS; ++cc) {
        cpwait<1>();
        __syncthreads();
        if (cc + 2 < CHUNKS) {
            static const uint32_t off3[3] = {0, STG, 2 * STG};
            stage(cc + 2, sbase + off3[(cc + 2) % 3]);
        }
        cpcommit();

        const uint32_t Ab = sbase + (uint32_t)((cc % 3) * STG);
        const uint32_t Bb = Ab + A_BYTES + (uint32_t)gate * BG_BYTES;

        #pragma unroll
        for (int ks = 0; ks < 4; ++ks) {
            uint32_t a[4][4];
            #pragma unroll
            for (int mi = 0; mi < 4; ++mi)
                ldsm4(a[mi], Ab + sw128((uint32_t)((warp_m + 16 * mi + (lane & 15)) * 128
                                                    + ks * 32 + ((lane >> 4) << 4))));
            uint32_t b[2][4];
            #pragma unroll
            for (int nb = 0; nb < 2; ++nb)
                ldsm4t(b[nb], Bb + (uint32_t)((ks * 16 + (lane & 15)) * BG_STRIDE
                                               + (nb * 16 + ((lane >> 4) << 3)) * 2));
            #pragma unroll
            for (int mi = 0; mi < 4; ++mi)
                #pragma unroll
                for (int j = 0; j < 4; ++j)
                    mma16(acc[mi][j], a[mi], b[j >> 1][(j & 1) * 2], b[j >> 1][(j & 1) * 2 + 1]);
        }
    }

    // -------- exchange z through smem (staging buffers are dead now) --------
    __syncthreads();
    float* zs = reinterpret_cast<float*>(smem);   // [4][128][36]
    #pragma unroll
    for (int mi = 0; mi < 4; ++mi) {
        #pragma unroll
        for (int j = 0; j < 4; ++j) {
            const int r = warp_m + 16 * mi + (lane >> 2);
            const int c = 8 * j + (lane & 3) * 2;
            float* p0 = zs + (uint32_t)gate * ZS_G + (uint32_t)r * 36 + c;
            p0[0] = acc[mi][j][0];
            p0[1] = acc[mi][j][1];
            float* p1 = p0 + 8 * 36;
            p1[0] = acc[mi][j][2];
            p1[1] = acc[mi][j][3];
        }
    }
    __syncthreads();

    // -------- combine: activations + h,c stores (coalesced float4) --------
    const float cf = (float)__ldg(caro);
    const int nloc = (tid & 7) * 4;
    const float4 b_f = *reinterpret_cast<const float4*>(bf + n0 + nloc);
    const float4 b_i = *reinterpret_cast<const float4*>(bi + n0 + nloc);
    const float4 b_o = *reinterpret_cast<const float4*>(bo + n0 + nloc);
    const float4 b_c = *reinterpret_cast<const float4*>(bc + n0 + nloc);

    #pragma unroll
    for (int p = 0; p < 4; ++p) {
        const int m = p * 32 + (tid >> 3);
        const uint32_t zoff = (uint32_t)m * 36 + nloc;
        const float4 zf = *reinterpret_cast<const float4*>(zs + 0 * ZS_G + zoff);
        const float4 zi = *reinterpret_cast<const float4*>(zs + 1 * ZS_G + zoff);
        const float4 zo = *reinterpret_cast<const float4*>(zs + 2 * ZS_G + zoff);
        const float4 zc = *reinterpret_cast<const float4*>(zs + 3 * ZS_G + zoff);

        float4 h4, c4;
        const float* pzf = &zf.x; const float* pzi = &zi.x;
        const float* pzo = &zo.x; const float* pzc = &zc.x;
        const float* pbf = &b_f.x; const float* pbi = &b_i.x;
        const float* pbo = &b_o.x; const float* pbc = &b_c.x;
        float* ph = &h4.x; float* pc = &c4.x;
        #pragma unroll
        for (int e = 0; e < 4; ++e) {
            const float f  = 1.f / (1.f + expf(-(pzf[e] + pbf[e])));
            const float ii = 1.f / (1.f + expf(-(pzi[e] + pbi[e])));
            const float oo = 1.f / (1.f + expf(-(pzo[e] + pbo[e])));
            const float gg = tanhf(pzc[e] + pbc[e]);
            const float cv = f * cf + ii * gg;
            pc[e] = cv;
            ph[e] = oo * cv;
        }
        const size_t o = (size_t)(m0 + m) * DIMK + n0 + nloc;
        *reinterpret_cast<float4*>(out + o) = h4;
        *reinterpret_cast<float4*>(out + PLANE + o) = c4;
    }
}

// ---------------- launch ----------------
extern "C" void kernel_launch(void* const* d_in, const int* in_sizes, int n_in,
                              void* d_out, int out_size) {
    (void)in_sizes; (void)n_in; (void)out_size;
    const float* X    = (const float*)d_in[0];
    const float* H    = (const float*)d_in[1];
    const int*   caro = (const int*)d_in[2];
    const float* Wfx = (const float*)d_in[3];
    const float* Wfh = (const float*)d_in[4];
    const float* bf  = (const float*)d_in[5];
    const float* Wix = (const float*)d_in[6];
    const float* Wih = (const float*)d_in[7];
    const float* bi  = (const float*)d_in[8];
    const float* Wox = (const float*)d_in[9];
    const float* Woh = (const float*)d_in[10];
    const float* bo  = (const float*)d_in[11];
    const float* Wcx = (const float*)d_in[12];
    const float* Wch = (const float*)d_in[13];
    const float* bc  = (const float*)d_in[14];
    float* out = (float*)d_out;

    cudaFuncSetAttribute(lstm_fused, cudaFuncAttributeMaxDynamicSharedMemorySize, SMEM_TOTAL);

    convXH<<<BATCH, 256>>>(X, H);
    convW<<<4 * KTOT, 128>>>(Wfx, Wfh, Wix, Wih, Wox, Woh, Wcx, Wch);
    lstm_fused<<<(BATCH / BM) * 32, THREADS, SMEM_TOTAL>>>(caro, bf, bi, bo, bc, out);
}

// round 9
// speedup vs baseline: 7.8421x; 1.0816x over previous
#include <cuda_runtime.h>
#include <cuda_fp16.h>
#include <cstdint>
#include <cstddef>

#define DI __device__ __forceinline__

// ---------------- constants ----------------
constexpr int BM = 128, BN = 32, BK = 64, THREADS = 256;
constexpr int DIMK = 1024;
constexpr int BATCH = 16384;
constexpr int KTOT = 2048;
constexpr int CHUNKS = 32;                        // 2048 / 64
constexpr size_t PLANE = (size_t)BATCH * DIMK;

// A: sw128-swizzled rows of 128B (64 halves). B: 4 gate tiles, 64k x 32n, stride 80.
constexpr uint32_t A_BYTES  = 128 * 128;          // 16384
constexpr uint32_t BG_STRIDE = 80;                // 64B data + 16B pad
constexpr uint32_t BG_BYTES  = 64 * BG_STRIDE;    // 5120 per gate
constexpr uint32_t B_BYTES   = 4 * BG_BYTES;      // 20480
constexpr uint32_t STG = A_BYTES + B_BYTES;       // 36864
constexpr uint32_t SMEM_TOTAL = 3 * STG;          // 110592 -> 2 CTAs/SM (216KB)

// z-exchange layout in reused smem: [gate][128][36] floats
constexpr uint32_t ZS_G = 128 * 36;

// ---------------- device scratch ----------------
__device__ __half g_XH[(size_t)BATCH * KTOT];     // [m][k]: X | H
__device__ __half g_W[(size_t)4 * KTOT * DIMK];   // [gate][k][n]

// ---------------- PTX helpers ----------------
DI uint32_t smem_u32(const void* p) {
    uint32_t a;
    asm("{ .reg .u64 t; cvta.to.shared.u64 t, %1; cvt.u32.u64 %0, t; }" : "=r"(a) : "l"(p));
    return a;
}
DI uint32_t sw128(uint32_t o) { return o ^ ((o >> 3) & 0x70); }
DI void cpasync16(uint32_t dst, const void* src) {
    asm volatile("cp.async.cg.shared.global [%0], [%1], 16;" :: "r"(dst), "l"(src) : "memory");
}
DI void cpcommit() { asm volatile("cp.async.commit_group;" ::: "memory"); }
template<int N> DI void cpwait() { asm volatile("cp.async.wait_group %0;" :: "n"(N) : "memory"); }
DI void ldsm4(uint32_t* r, uint32_t a) {
    asm volatile("ldmatrix.sync.aligned.m8n8.x4.shared.b16 {%0,%1,%2,%3}, [%4];"
                 : "=r"(r[0]), "=r"(r[1]), "=r"(r[2]), "=r"(r[3]) : "r"(a));
}
DI void ldsm4t(uint32_t* r, uint32_t a) {
    asm volatile("ldmatrix.sync.aligned.m8n8.x4.trans.shared.b16 {%0,%1,%2,%3}, [%4];"
                 : "=r"(r[0]), "=r"(r[1]), "=r"(r[2]), "=r"(r[3]) : "r"(a));
}
DI void mma16(float* d, const uint32_t* a, uint32_t b0, uint32_t b1) {
    asm volatile(
        "mma.sync.aligned.m16n8k16.row.col.f32.f16.f16.f32 "
        "{%0,%1,%2,%3},{%4,%5,%6,%7},{%8,%9},{%0,%1,%2,%3};"
        : "+f"(d[0]), "+f"(d[1]), "+f"(d[2]), "+f"(d[3])
        : "r"(a[0]), "r"(a[1]), "r"(a[2]), "r"(a[3]), "r"(b0), "r"(b1));
}

// ---------------- prep: fp16 conversion ----------------
__global__ void __launch_bounds__(256)
convXH(const float* __restrict__ X, const float* __restrict__ H)
{
    const int m = blockIdx.x, t = threadIdx.x;
    const float* src = (t < 128) ? X + (size_t)m * 1024 + 8 * t
                                 : H + (size_t)m * 1024 + 8 * (t - 128);
    const float4 v0 = reinterpret_cast<const float4*>(src)[0];
    const float4 v1 = reinterpret_cast<const float4*>(src)[1];
    __half2 h[4];
    h[0] = __floats2half2_rn(v0.x, v0.y);
    h[1] = __floats2half2_rn(v0.z, v0.w);
    h[2] = __floats2half2_rn(v1.x, v1.y);
    h[3] = __floats2half2_rn(v1.z, v1.w);
    *reinterpret_cast<uint4*>(g_XH + (size_t)m * KTOT + 8 * t) = *reinterpret_cast<uint4*>(h);
}

__global__ void __launch_bounds__(128)
convW(const float* __restrict__ Wfx, const float* __restrict__ Wfh,
      const float* __restrict__ Wix, const float* __restrict__ Wih,
      const float* __restrict__ Wox, const float* __restrict__ Woh,
      const float* __restrict__ Wcx, const float* __restrict__ Wch)
{
    const int gate = blockIdx.x >> 11;
    const int k = blockIdx.x & 2047;
    const int t = threadIdx.x;
    const float* Wx = (gate == 0) ? Wfx : (gate == 1) ? Wix : (gate == 2) ? Wox : Wcx;
    const float* Wh = (gate == 0) ? Wfh : (gate == 1) ? Wih : (gate == 2) ? Woh : Wch;
    const float* src = ((k < 1024) ? Wx + (size_t)k * 1024 : Wh + (size_t)(k - 1024) * 1024) + 8 * t;
    const float4 v0 = reinterpret_cast<const float4*>(src)[0];
    const float4 v1 = reinterpret_cast<const float4*>(src)[1];
    __half2 h[4];
    h[0] = __floats2half2_rn(v0.x, v0.y);
    h[1] = __floats2half2_rn(v0.z, v0.w);
    h[2] = __floats2half2_rn(v1.x, v1.y);
    h[3] = __floats2half2_rn(v1.z, v1.w);
    *reinterpret_cast<uint4*>(g_W + ((size_t)gate * KTOT + k) * DIMK + 8 * t) =
        *reinterpret_cast<uint4*>(h);
}

// ---------------- fused GEMM + LSTM cell ----------------
__global__ void __launch_bounds__(THREADS, 2)
lstm_fused(const int* __restrict__ caro,
           const float* __restrict__ bf, const float* __restrict__ bi,
           const float* __restrict__ bo, const float* __restrict__ bc,
           float* __restrict__ out)
{
    extern __shared__ __align__(1024) char smem[];
    const uint32_t sbase = smem_u32(smem);
    const int tid = threadIdx.x, wid = tid >> 5, lane = tid & 31;

    const int n0 = (blockIdx.x & 31) * BN;
    const int m0 = (blockIdx.x >> 5) * BM;

    const int gate   = wid >> 1;                  // warp -> gate
    const int warp_m = (wid & 1) * 64;            // warp -> m half

    float acc[4][4][4];
    #pragma unroll
    for (int mi = 0; mi < 4; ++mi)
        #pragma unroll
        for (int j = 0; j < 4; ++j)
            #pragma unroll
            for (int e = 0; e < 4; ++e) acc[mi][j][e] = 0.f;

    // staging halves: A in two parts (i = 0,1 / 2,3), B in two parts
    auto stageA = [&](int cs, uint32_t sb, int half) {
        const int k0 = cs * BK;
        #pragma unroll
        for (int i = half * 2; i < half * 2 + 2; ++i) {
            const int idx = i * THREADS + tid;
            const int r = idx >> 3, c = idx & 7;
            cpasync16(sb + sw128((uint32_t)(r * 128 + c * 16)),
                      g_XH + (size_t)(m0 + r) * KTOT + k0 + c * 8);
        }
    };
    auto stageB = [&](int cs, uint32_t sb, int half) {
        const int k0 = cs * BK;
        #pragma unroll
        for (int i = half * 2; i < half * 2 + 2; ++i) {
            const int idx = i * THREADS + tid;
            const int g = idx >> 8, u = idx & 255;
            const int r = u >> 2, c = u & 3;
            cpasync16(sb + A_BYTES + (uint32_t)g * BG_BYTES + (uint32_t)(r * BG_STRIDE + c * 16),
                      g_W + ((size_t)g * KTOT + k0 + r) * DIMK + n0 + c * 8);
        }
    };
    auto stageAll = [&](int cs, uint32_t sb) {
        stageA(cs, sb, 0); stageA(cs, sb, 1);
        stageB(cs, sb, 0); stageB(cs, sb, 1);
    };

    stageAll(0, sbase);        cpcommit();
    stageAll(1, sbase + STG);  cpcommit();

    #pragma unroll 1
    for (int cc = 0; cc < CHUNKS; ++cc) {
        cpwait<1>();
        __syncthreads();

        const uint32_t Ab = sbase + (uint32_t)((cc % 3) * STG);
        const uint32_t Bb = Ab + A_BYTES + (uint32_t)gate * BG_BYTES;
        const bool pf = (cc + 2 < CHUNKS);
        const uint32_t sbN = sbase + (uint32_t)(((cc + 2) % 3) * STG);

        #pragma unroll
        for (int ks = 0; ks < 4; ++ks) {
            uint32_t a[4][4];
            #pragma unroll
            for (int mi = 0; mi < 4; ++mi)
                ldsm4(a[mi], Ab + sw128((uint32_t)((warp_m + 16 * mi + (lane & 15)) * 128
                                                    + ks * 32 + ((lane >> 4) << 4))));
            uint32_t b[2][4];
            #pragma unroll
            for (int nb = 0; nb < 2; ++nb)
                ldsm4t(b[nb], Bb + (uint32_t)((ks * 16 + (lane & 15)) * BG_STRIDE
                                               + (nb * 16 + ((lane >> 4) << 3)) * 2));

            // interleaved staging of chunk cc+2: smooth LTS demand
            if (pf) {
                if (ks == 0)      stageA(cc + 2, sbN, 0);
                else if (ks == 1) stageA(cc + 2, sbN, 1);
                else if (ks == 2) stageB(cc + 2, sbN, 0);
                else              stageB(cc + 2, sbN, 1);
            }

            #pragma unroll
            for (int mi = 0; mi < 4; ++mi)
                #pragma unroll
                for (int j = 0; j < 4; ++j)
                    mma16(acc[mi][j], a[mi], b[j >> 1][(j & 1) * 2], b[j >> 1][(j & 1) * 2 + 1]);
        }
        cpcommit();
    }

    // -------- exchange z through smem (staging buffers dead) --------
    __syncthreads();
    float* zs = reinterpret_cast<float*>(smem);   // [4][128][36]
    #pragma unroll
    for (int mi = 0; mi < 4; ++mi) {
        #pragma unroll
        for (int j = 0; j < 4; ++j) {
            const int r = warp_m + 16 * mi + (lane >> 2);
            const int c = 8 * j + (lane & 3) * 2;
            float* p0 = zs + (uint32_t)gate * ZS_G + (uint32_t)r * 36 + c;
            p0[0] = acc[mi][j][0];
            p0[1] = acc[mi][j][1];
            float* p1 = p0 + 8 * 36;
            p1[0] = acc[mi][j][2];
            p1[1] = acc[mi][j][3];
        }
    }
    __syncthreads();

    // -------- combine: activations + h,c stores --------
    const float cf = (float)__ldg(caro);
    const int nloc = (tid & 7) * 4;
    const float4 b_f = *reinterpret_cast<const float4*>(bf + n0 + nloc);
    const float4 b_i = *reinterpret_cast<const float4*>(bi + n0 + nloc);
    const float4 b_o = *reinterpret_cast<const float4*>(bo + n0 + nloc);
    const float4 b_c = *reinterpret_cast<const float4*>(bc + n0 + nloc);

    #pragma unroll
    for (int p = 0; p < 4; ++p) {
        const int m = p * 32 + (tid >> 3);
        const uint32_t zoff = (uint32_t)m * 36 + nloc;
        const float4 zf = *reinterpret_cast<const float4*>(zs + 0 * ZS_G + zoff);
        const float4 zi = *reinterpret_cast<const float4*>(zs + 1 * ZS_G + zoff);
        const float4 zo = *reinterpret_cast<const float4*>(zs + 2 * ZS_G + zoff);
        const float4 zc = *reinterpret_cast<const float4*>(zs + 3 * ZS_G + zoff);

        float4 h4, c4;
        const float* pzf = &zf.x; const float* pzi = &zi.x;
        const float* pzo = &zo.x; const float* pzc = &zc.x;
        const float* pbf = &b_f.x; const float* pbi = &b_i.x;
        const float* pbo = &b_o.x; const float* pbc = &b_c.x;
        float* ph = &h4.x; float* pc = &c4.x;
        #pragma unroll
        for (int e = 0; e < 4; ++e) {
            const float f  = 1.f / (1.f + expf(-(pzf[e] + pbf[e])));
            const float ii = 1.f / (1.f + expf(-(pzi[e] + pbi[e])));
            const float oo = 1.f / (1.f + expf(-(pzo[e] + pbo[e])));
            const float gg = tanhf(pzc[e] + pbc[e]);
            const float cv = f * cf + ii * gg;
            pc[e] = cv;
            ph[e] = oo * cv;
        }
        const size_t o = (size_t)(m0 + m) * DIMK + n0 + nloc;
        *reinterpret_cast<float4*>(out + o) = h4;
        *reinterpret_cast<float4*>(out + PLANE + o) = c4;
    }
}

// ---------------- launch ----------------
extern "C" void kernel_launch(void* const* d_in, const int* in_sizes, int n_in,
                              void* d_out, int out_size) {
    (void)in_sizes; (void)n_in; (void)out_size;
    const float* X    = (const float*)d_in[0];
    const float* H    = (const float*)d_in[1];
    const int*   caro = (const int*)d_in[2];
    const float* Wfx = (const float*)d_in[3];
    const float* Wfh = (const float*)d_in[4];
    const float* bf  = (const float*)d_in[5];
    const float* Wix = (const float*)d_in[6];
    const float* Wih = (const float*)d_in[7];
    const float* bi  = (const float*)d_in[8];
    const float* Wox = (const float*)d_in[9];
    const float* Woh = (const float*)d_in[10];
    const float* bo  = (const float*)d_in[11];
    const float* Wcx = (const float*)d_in[12];
    const float* Wch = (const float*)d_in[13];
    const float* bc  = (const float*)d_in[14];
    float* out = (float*)d_out;

    cudaFuncSetAttribute(lstm_fused, cudaFuncAttributeMaxDynamicSharedMemorySize, SMEM_TOTAL);

    convXH<<<BATCH, 256>>>(X, H);
    convW<<<4 * KTOT, 128>>>(Wfx, Wfh, Wix, Wih, Wox, Woh, Wcx, Wch);
    lstm_fused<<<(BATCH / BM) * 32, THREADS, SMEM_TOTAL>>>(caro, bf, bi, bo, bc, out);
}